// round 1
// baseline (speedup 1.0000x reference)
#include <cuda_runtime.h>

#define NN 50000
#define NE 640000

// 25.6 MB scratch accumulator for segment-sum (device global: alloc-free).
__device__ float g_agg[(size_t)NN * 128];

// ---- packed fp32x2 helpers (sm_103a) ----
static __device__ __forceinline__ unsigned long long pk2(float lo, float hi) {
    unsigned long long r;
    asm("mov.b64 %0, {%1,%2};" : "=l"(r) : "f"(lo), "f"(hi));
    return r;
}
static __device__ __forceinline__ void upk2(unsigned long long v, float &lo, float &hi) {
    asm("mov.b64 {%0,%1}, %2;" : "=f"(lo), "=f"(hi) : "l"(v));
}
static __device__ __forceinline__ void fma2(unsigned long long &d,
                                            unsigned long long a,
                                            unsigned long long b) {
    asm("fma.rn.f32x2 %0, %1, %2, %0;" : "+l"(d) : "l"(a), "l"(b));
}

// ---- kernel 0: zero the aggregation buffer ----
__global__ void zero_agg_kernel() {
    size_t stride = (size_t)gridDim.x * blockDim.x * 4;
    for (size_t i = (size_t)(blockIdx.x * blockDim.x + threadIdx.x) * 4;
         i < (size_t)NN * 128; i += stride) {
        *reinterpret_cast<float4 *>(&g_agg[i]) = make_float4(0.f, 0.f, 0.f, 0.f);
    }
}

// ---- kernel 1: edge MLP + scatter-add ----
// Tile: 64 edges x 128 cols per block, 256 threads, 8x4 micro-tile per thread.
// X rows are gathered on the fly: [node_h[src] | node_h[dst] | edge_h].
__global__ __launch_bounds__(256)
void edge_kernel(const float *__restrict__ node_h, const float *__restrict__ edge_h,
                 const int *__restrict__ src, const int *__restrict__ dst,
                 const float *__restrict__ We1, const float *__restrict__ be1,
                 const float *__restrict__ We2, const float *__restrict__ be2) {
    // S: first used as X tile (64 rows, K-slab of 32, padded stride 36 = 144B, 16B-aligned),
    //    then reused as y1 tile (64 x 128, stride 128).
    __shared__ __align__(16) float S[64 * 128];
    __shared__ __align__(16) float Ws[32 * 128];

    const int tid  = threadIdx.x;
    const int colg = tid & 31;        // 0..31 -> cols colg*4..+3
    const int rowg = tid >> 5;        // 0..7  -> rows rowg*8..+7
    const int c0 = colg << 2;
    const int r0 = rowg << 3;
    const int ebase = blockIdx.x << 6;

    // ---------- GEMM1: y1 = relu(X @ We1 + be1),  K = 384 ----------
    unsigned long long acc[8][2];
    {
        float4 b = *reinterpret_cast<const float4 *>(&be1[c0]);
        unsigned long long i0 = pk2(b.x, b.y), i1 = pk2(b.z, b.w);
#pragma unroll
        for (int r = 0; r < 8; r++) { acc[r][0] = i0; acc[r][1] = i1; }
    }

    for (int kt = 0; kt < 12; ++kt) {
        const int k0 = kt << 5;
        // Load X tile: 512 float4s, 2 per thread. A 32-wide K slab never
        // straddles a concat segment boundary (segments at 0/128/256).
#pragma unroll
        for (int i = 0; i < 2; i++) {
            int li  = tid + (i << 8);
            int row = li >> 3;
            int kk  = (li & 7) << 2;
            int e   = ebase + row;
            int k   = k0 + kk;
            const float *p;
            if (k < 128)       p = node_h + (size_t)src[e] * 128 + k;
            else if (k < 256)  p = node_h + (size_t)dst[e] * 128 + (k - 128);
            else               p = edge_h + (size_t)e * 128 + (k - 256);
            *reinterpret_cast<float4 *>(&S[row * 36 + kk]) =
                *reinterpret_cast<const float4 *>(p);
        }
        // Load W tile (32 x 128), coalesced.
#pragma unroll
        for (int i = 0; i < 4; i++) {
            int li = tid + (i << 8);
            int wr = li >> 5;
            int wc = (li & 31) << 2;
            *reinterpret_cast<float4 *>(&Ws[wr * 128 + wc]) =
                *reinterpret_cast<const float4 *>(&We1[(size_t)(k0 + wr) * 128 + wc]);
        }
        __syncthreads();
#pragma unroll
        for (int kk = 0; kk < 32; kk++) {
            ulonglong2 b = *reinterpret_cast<const ulonglong2 *>(&Ws[kk * 128 + c0]);
#pragma unroll
            for (int r = 0; r < 8; r++) {
                float a = S[(r0 + r) * 36 + kk];        // warp-broadcast LDS
                unsigned long long aa = pk2(a, a);
                fma2(acc[r][0], aa, b.x);
                fma2(acc[r][1], aa, b.y);
            }
        }
        __syncthreads();
    }

    // relu + stash y1 tile back into S (stride 128); each thread writes its own cells.
#pragma unroll
    for (int r = 0; r < 8; r++) {
        float f0, f1, f2, f3;
        upk2(acc[r][0], f0, f1);
        upk2(acc[r][1], f2, f3);
        float4 v = make_float4(fmaxf(f0, 0.f), fmaxf(f1, 0.f),
                               fmaxf(f2, 0.f), fmaxf(f3, 0.f));
        *reinterpret_cast<float4 *>(&S[(r0 + r) * 128 + c0]) = v;
    }

    // ---------- GEMM2: y2 = y1 @ We2 + be2,  K = 128 ----------
    unsigned long long acc2[8][2];
    {
        float4 b = *reinterpret_cast<const float4 *>(&be2[c0]);
        unsigned long long i0 = pk2(b.x, b.y), i1 = pk2(b.z, b.w);
#pragma unroll
        for (int r = 0; r < 8; r++) { acc2[r][0] = i0; acc2[r][1] = i1; }
    }
    __syncthreads();   // y1 visible to all; Ws free to overwrite

    for (int kt = 0; kt < 4; ++kt) {
        const int k0 = kt << 5;
#pragma unroll
        for (int i = 0; i < 4; i++) {
            int li = tid + (i << 8);
            int wr = li >> 5;
            int wc = (li & 31) << 2;
            *reinterpret_cast<float4 *>(&Ws[wr * 128 + wc]) =
                *reinterpret_cast<const float4 *>(&We2[(size_t)(k0 + wr) * 128 + wc]);
        }
        __syncthreads();
#pragma unroll
        for (int kk = 0; kk < 32; kk++) {
            ulonglong2 b = *reinterpret_cast<const ulonglong2 *>(&Ws[kk * 128 + c0]);
#pragma unroll
            for (int r = 0; r < 8; r++) {
                float a = S[(r0 + r) * 128 + (k0 + kk)];
                unsigned long long aa = pk2(a, a);
                fma2(acc2[r][0], aa, b.x);
                fma2(acc2[r][1], aa, b.y);
            }
        }
        __syncthreads();
    }

    // ---------- scatter-add to g_agg[dst] ----------
#pragma unroll
    for (int r = 0; r < 8; r++) {
        int dn = dst[ebase + r0 + r];
        float *p = g_agg + (size_t)dn * 128 + c0;
        float f0, f1, f2, f3;
        upk2(acc2[r][0], f0, f1);
        upk2(acc2[r][1], f2, f3);
        atomicAdd(p + 0, f0);
        atomicAdd(p + 1, f1);
        atomicAdd(p + 2, f2);
        atomicAdd(p + 3, f3);
    }
}

// ---- kernel 2: node MLP ----
// X = [agg | node_h], K = 256; same tiling, direct store to out.
__global__ __launch_bounds__(256)
void node_kernel(const float *__restrict__ node_h,
                 const float *__restrict__ Wn1, const float *__restrict__ bn1,
                 const float *__restrict__ Wn2, const float *__restrict__ bn2,
                 float *__restrict__ out) {
    __shared__ __align__(16) float S[64 * 128];
    __shared__ __align__(16) float Ws[32 * 128];

    const int tid  = threadIdx.x;
    const int colg = tid & 31;
    const int rowg = tid >> 5;
    const int c0 = colg << 2;
    const int r0 = rowg << 3;
    const int nbase = blockIdx.x << 6;

    unsigned long long acc[8][2];
    {
        float4 b = *reinterpret_cast<const float4 *>(&bn1[c0]);
        unsigned long long i0 = pk2(b.x, b.y), i1 = pk2(b.z, b.w);
#pragma unroll
        for (int r = 0; r < 8; r++) { acc[r][0] = i0; acc[r][1] = i1; }
    }

    for (int kt = 0; kt < 8; ++kt) {
        const int k0 = kt << 5;
#pragma unroll
        for (int i = 0; i < 2; i++) {
            int li  = tid + (i << 8);
            int row = li >> 3;
            int kk  = (li & 7) << 2;
            int k   = k0 + kk;
            int n   = nbase + row;
            float4 v = make_float4(0.f, 0.f, 0.f, 0.f);
            if (n < NN) {
                const float *p = (k < 128)
                    ? (g_agg + (size_t)n * 128 + k)
                    : (node_h + (size_t)n * 128 + (k - 128));
                v = *reinterpret_cast<const float4 *>(p);
            }
            *reinterpret_cast<float4 *>(&S[row * 36 + kk]) = v;
        }
#pragma unroll
        for (int i = 0; i < 4; i++) {
            int li = tid + (i << 8);
            int wr = li >> 5;
            int wc = (li & 31) << 2;
            *reinterpret_cast<float4 *>(&Ws[wr * 128 + wc]) =
                *reinterpret_cast<const float4 *>(&Wn1[(size_t)(k0 + wr) * 128 + wc]);
        }
        __syncthreads();
#pragma unroll
        for (int kk = 0; kk < 32; kk++) {
            ulonglong2 b = *reinterpret_cast<const ulonglong2 *>(&Ws[kk * 128 + c0]);
#pragma unroll
            for (int r = 0; r < 8; r++) {
                float a = S[(r0 + r) * 36 + kk];
                unsigned long long aa = pk2(a, a);
                fma2(acc[r][0], aa, b.x);
                fma2(acc[r][1], aa, b.y);
            }
        }
        __syncthreads();
    }

#pragma unroll
    for (int r = 0; r < 8; r++) {
        float f0, f1, f2, f3;
        upk2(acc[r][0], f0, f1);
        upk2(acc[r][1], f2, f3);
        float4 v = make_float4(fmaxf(f0, 0.f), fmaxf(f1, 0.f),
                               fmaxf(f2, 0.f), fmaxf(f3, 0.f));
        *reinterpret_cast<float4 *>(&S[(r0 + r) * 128 + c0]) = v;
    }

    unsigned long long acc2[8][2];
    {
        float4 b = *reinterpret_cast<const float4 *>(&bn2[c0]);
        unsigned long long i0 = pk2(b.x, b.y), i1 = pk2(b.z, b.w);
#pragma unroll
        for (int r = 0; r < 8; r++) { acc2[r][0] = i0; acc2[r][1] = i1; }
    }
    __syncthreads();

    for (int kt = 0; kt < 4; ++kt) {
        const int k0 = kt << 5;
#pragma unroll
        for (int i = 0; i < 4; i++) {
            int li = tid + (i << 8);
            int wr = li >> 5;
            int wc = (li & 31) << 2;
            *reinterpret_cast<float4 *>(&Ws[wr * 128 + wc]) =
                *reinterpret_cast<const float4 *>(&Wn2[(size_t)(k0 + wr) * 128 + wc]);
        }
        __syncthreads();
#pragma unroll
        for (int kk = 0; kk < 32; kk++) {
            ulonglong2 b = *reinterpret_cast<const ulonglong2 *>(&Ws[kk * 128 + c0]);
#pragma unroll
            for (int r = 0; r < 8; r++) {
                float a = S[(r0 + r) * 128 + (k0 + kk)];
                unsigned long long aa = pk2(a, a);
                fma2(acc2[r][0], aa, b.x);
                fma2(acc2[r][1], aa, b.y);
            }
        }
        __syncthreads();
    }

#pragma unroll
    for (int r = 0; r < 8; r++) {
        int n = nbase + r0 + r;
        if (n < NN) {
            float f0, f1, f2, f3;
            upk2(acc2[r][0], f0, f1);
            upk2(acc2[r][1], f2, f3);
            *reinterpret_cast<float4 *>(&out[(size_t)n * 128 + c0]) =
                make_float4(f0, f1, f2, f3);
        }
    }
}

extern "C" void kernel_launch(void *const *d_in, const int *in_sizes, int n_in,
                              void *d_out, int out_size) {
    const float *node_h = (const float *)d_in[0];
    const float *edge_h = (const float *)d_in[1];
    const int   *src    = (const int *)d_in[2];
    const int   *dst    = (const int *)d_in[3];
    const float *We1    = (const float *)d_in[4];
    const float *be1    = (const float *)d_in[5];
    const float *We2    = (const float *)d_in[6];
    const float *be2    = (const float *)d_in[7];
    const float *Wn1    = (const float *)d_in[8];
    const float *bn1    = (const float *)d_in[9];
    const float *Wn2    = (const float *)d_in[10];
    const float *bn2    = (const float *)d_in[11];
    float *out = (float *)d_out;

    zero_agg_kernel<<<1024, 256>>>();
    edge_kernel<<<NE / 64, 256>>>(node_h, edge_h, src, dst, We1, be1, We2, be2);
    node_kernel<<<(NN + 63) / 64, 256>>>(node_h, Wn1, bn1, Wn2, bn2, out);
}

// round 2
// speedup vs baseline: 1.0007x; 1.0007x over previous
#include <cuda_runtime.h>

#define NN 50000
#define NE 640000

// 25.6 MB scratch accumulator for segment-sum (device global: alloc-free).
__device__ float g_agg[(size_t)NN * 128];

// ---- packed fp32x2 helpers (sm_103a) ----
static __device__ __forceinline__ unsigned long long pk2(float lo, float hi) {
    unsigned long long r;
    asm("mov.b64 %0, {%1,%2};" : "=l"(r) : "f"(lo), "f"(hi));
    return r;
}
static __device__ __forceinline__ void upk2(unsigned long long v, float &lo, float &hi) {
    asm("mov.b64 {%0,%1}, %2;" : "=f"(lo), "=f"(hi) : "l"(v));
}
static __device__ __forceinline__ void fma2(unsigned long long &d,
                                            unsigned long long a,
                                            unsigned long long b) {
    asm("fma.rn.f32x2 %0, %1, %2, %0;" : "+l"(d) : "l"(a), "l"(b));
}

// ---- kernel 0: zero the aggregation buffer ----
__global__ void zero_agg_kernel() {
    size_t stride = (size_t)gridDim.x * blockDim.x * 4;
    for (size_t i = (size_t)(blockIdx.x * blockDim.x + threadIdx.x) * 4;
         i < (size_t)NN * 128; i += stride) {
        *reinterpret_cast<float4 *>(&g_agg[i]) = make_float4(0.f, 0.f, 0.f, 0.f);
    }
}

// ---- kernel 1: edge MLP + scatter-add ----
// Tile: 64 edges x 128 cols per block, 256 threads, 8x4 micro-tile per thread.
// X rows are gathered on the fly: [node_h[src] | node_h[dst] | edge_h].
__global__ __launch_bounds__(256)
void edge_kernel(const float *__restrict__ node_h, const float *__restrict__ edge_h,
                 const int *__restrict__ src, const int *__restrict__ dst,
                 const float *__restrict__ We1, const float *__restrict__ be1,
                 const float *__restrict__ We2, const float *__restrict__ be2) {
    // S: first used as X tile (64 rows, K-slab of 32, padded stride 36 = 144B, 16B-aligned),
    //    then reused as y1 tile (64 x 128, stride 128).
    __shared__ __align__(16) float S[64 * 128];
    __shared__ __align__(16) float Ws[32 * 128];

    const int tid  = threadIdx.x;
    const int colg = tid & 31;        // 0..31 -> cols colg*4..+3
    const int rowg = tid >> 5;        // 0..7  -> rows rowg*8..+7
    const int c0 = colg << 2;
    const int r0 = rowg << 3;
    const int ebase = blockIdx.x << 6;

    // ---------- GEMM1: y1 = relu(X @ We1 + be1),  K = 384 ----------
    unsigned long long acc[8][2];
    {
        float4 b = *reinterpret_cast<const float4 *>(&be1[c0]);
        unsigned long long i0 = pk2(b.x, b.y), i1 = pk2(b.z, b.w);
#pragma unroll
        for (int r = 0; r < 8; r++) { acc[r][0] = i0; acc[r][1] = i1; }
    }

    for (int kt = 0; kt < 12; ++kt) {
        const int k0 = kt << 5;
        // Load X tile: 512 float4s, 2 per thread. A 32-wide K slab never
        // straddles a concat segment boundary (segments at 0/128/256).
#pragma unroll
        for (int i = 0; i < 2; i++) {
            int li  = tid + (i << 8);
            int row = li >> 3;
            int kk  = (li & 7) << 2;
            int e   = ebase + row;
            int k   = k0 + kk;
            const float *p;
            if (k < 128)       p = node_h + (size_t)src[e] * 128 + k;
            else if (k < 256)  p = node_h + (size_t)dst[e] * 128 + (k - 128);
            else               p = edge_h + (size_t)e * 128 + (k - 256);
            *reinterpret_cast<float4 *>(&S[row * 36 + kk]) =
                *reinterpret_cast<const float4 *>(p);
        }
        // Load W tile (32 x 128), coalesced.
#pragma unroll
        for (int i = 0; i < 4; i++) {
            int li = tid + (i << 8);
            int wr = li >> 5;
            int wc = (li & 31) << 2;
            *reinterpret_cast<float4 *>(&Ws[wr * 128 + wc]) =
                *reinterpret_cast<const float4 *>(&We1[(size_t)(k0 + wr) * 128 + wc]);
        }
        __syncthreads();
#pragma unroll
        for (int kk = 0; kk < 32; kk++) {
            ulonglong2 b = *reinterpret_cast<const ulonglong2 *>(&Ws[kk * 128 + c0]);
#pragma unroll
            for (int r = 0; r < 8; r++) {
                float a = S[(r0 + r) * 36 + kk];        // warp-broadcast LDS
                unsigned long long aa = pk2(a, a);
                fma2(acc[r][0], aa, b.x);
                fma2(acc[r][1], aa, b.y);
            }
        }
        __syncthreads();
    }

    // relu + stash y1 tile back into S (stride 128); each thread writes its own cells.
#pragma unroll
    for (int r = 0; r < 8; r++) {
        float f0, f1, f2, f3;
        upk2(acc[r][0], f0, f1);
        upk2(acc[r][1], f2, f3);
        float4 v = make_float4(fmaxf(f0, 0.f), fmaxf(f1, 0.f),
                               fmaxf(f2, 0.f), fmaxf(f3, 0.f));
        *reinterpret_cast<float4 *>(&S[(r0 + r) * 128 + c0]) = v;
    }

    // ---------- GEMM2: y2 = y1 @ We2 + be2,  K = 128 ----------
    unsigned long long acc2[8][2];
    {
        float4 b = *reinterpret_cast<const float4 *>(&be2[c0]);
        unsigned long long i0 = pk2(b.x, b.y), i1 = pk2(b.z, b.w);
#pragma unroll
        for (int r = 0; r < 8; r++) { acc2[r][0] = i0; acc2[r][1] = i1; }
    }
    __syncthreads();   // y1 visible to all; Ws free to overwrite

    for (int kt = 0; kt < 4; ++kt) {
        const int k0 = kt << 5;
#pragma unroll
        for (int i = 0; i < 4; i++) {
            int li = tid + (i << 8);
            int wr = li >> 5;
            int wc = (li & 31) << 2;
            *reinterpret_cast<float4 *>(&Ws[wr * 128 + wc]) =
                *reinterpret_cast<const float4 *>(&We2[(size_t)(k0 + wr) * 128 + wc]);
        }
        __syncthreads();
#pragma unroll
        for (int kk = 0; kk < 32; kk++) {
            ulonglong2 b = *reinterpret_cast<const ulonglong2 *>(&Ws[kk * 128 + c0]);
#pragma unroll
            for (int r = 0; r < 8; r++) {
                float a = S[(r0 + r) * 128 + (k0 + kk)];
                unsigned long long aa = pk2(a, a);
                fma2(acc2[r][0], aa, b.x);
                fma2(acc2[r][1], aa, b.y);
            }
        }
        __syncthreads();
    }

    // ---------- scatter-add to g_agg[dst] ----------
#pragma unroll
    for (int r = 0; r < 8; r++) {
        int dn = dst[ebase + r0 + r];
        float *p = g_agg + (size_t)dn * 128 + c0;
        float f0, f1, f2, f3;
        upk2(acc2[r][0], f0, f1);
        upk2(acc2[r][1], f2, f3);
        atomicAdd(p + 0, f0);
        atomicAdd(p + 1, f1);
        atomicAdd(p + 2, f2);
        atomicAdd(p + 3, f3);
    }
}

// ---- kernel 2: node MLP ----
// X = [agg | node_h], K = 256; same tiling, direct store to out.
__global__ __launch_bounds__(256)
void node_kernel(const float *__restrict__ node_h,
                 const float *__restrict__ Wn1, const float *__restrict__ bn1,
                 const float *__restrict__ Wn2, const float *__restrict__ bn2,
                 float *__restrict__ out) {
    __shared__ __align__(16) float S[64 * 128];
    __shared__ __align__(16) float Ws[32 * 128];

    const int tid  = threadIdx.x;
    const int colg = tid & 31;
    const int rowg = tid >> 5;
    const int c0 = colg << 2;
    const int r0 = rowg << 3;
    const int nbase = blockIdx.x << 6;

    unsigned long long acc[8][2];
    {
        float4 b = *reinterpret_cast<const float4 *>(&bn1[c0]);
        unsigned long long i0 = pk2(b.x, b.y), i1 = pk2(b.z, b.w);
#pragma unroll
        for (int r = 0; r < 8; r++) { acc[r][0] = i0; acc[r][1] = i1; }
    }

    for (int kt = 0; kt < 8; ++kt) {
        const int k0 = kt << 5;
#pragma unroll
        for (int i = 0; i < 2; i++) {
            int li  = tid + (i << 8);
            int row = li >> 3;
            int kk  = (li & 7) << 2;
            int k   = k0 + kk;
            int n   = nbase + row;
            float4 v = make_float4(0.f, 0.f, 0.f, 0.f);
            if (n < NN) {
                const float *p = (k < 128)
                    ? (g_agg + (size_t)n * 128 + k)
                    : (node_h + (size_t)n * 128 + (k - 128));
                v = *reinterpret_cast<const float4 *>(p);
            }
            *reinterpret_cast<float4 *>(&S[row * 36 + kk]) = v;
        }
#pragma unroll
        for (int i = 0; i < 4; i++) {
            int li = tid + (i << 8);
            int wr = li >> 5;
            int wc = (li & 31) << 2;
            *reinterpret_cast<float4 *>(&Ws[wr * 128 + wc]) =
                *reinterpret_cast<const float4 *>(&Wn1[(size_t)(k0 + wr) * 128 + wc]);
        }
        __syncthreads();
#pragma unroll
        for (int kk = 0; kk < 32; kk++) {
            ulonglong2 b = *reinterpret_cast<const ulonglong2 *>(&Ws[kk * 128 + c0]);
#pragma unroll
            for (int r = 0; r < 8; r++) {
                float a = S[(r0 + r) * 36 + kk];
                unsigned long long aa = pk2(a, a);
                fma2(acc[r][0], aa, b.x);
                fma2(acc[r][1], aa, b.y);
            }
        }
        __syncthreads();
    }

#pragma unroll
    for (int r = 0; r < 8; r++) {
        float f0, f1, f2, f3;
        upk2(acc[r][0], f0, f1);
        upk2(acc[r][1], f2, f3);
        float4 v = make_float4(fmaxf(f0, 0.f), fmaxf(f1, 0.f),
                               fmaxf(f2, 0.f), fmaxf(f3, 0.f));
        *reinterpret_cast<float4 *>(&S[(r0 + r) * 128 + c0]) = v;
    }

    unsigned long long acc2[8][2];
    {
        float4 b = *reinterpret_cast<const float4 *>(&bn2[c0]);
        unsigned long long i0 = pk2(b.x, b.y), i1 = pk2(b.z, b.w);
#pragma unroll
        for (int r = 0; r < 8; r++) { acc2[r][0] = i0; acc2[r][1] = i1; }
    }
    __syncthreads();

    for (int kt = 0; kt < 4; ++kt) {
        const int k0 = kt << 5;
#pragma unroll
        for (int i = 0; i < 4; i++) {
            int li = tid + (i << 8);
            int wr = li >> 5;
            int wc = (li & 31) << 2;
            *reinterpret_cast<float4 *>(&Ws[wr * 128 + wc]) =
                *reinterpret_cast<const float4 *>(&Wn2[(size_t)(k0 + wr) * 128 + wc]);
        }
        __syncthreads();
#pragma unroll
        for (int kk = 0; kk < 32; kk++) {
            ulonglong2 b = *reinterpret_cast<const ulonglong2 *>(&Ws[kk * 128 + c0]);
#pragma unroll
            for (int r = 0; r < 8; r++) {
                float a = S[(r0 + r) * 128 + (k0 + kk)];
                unsigned long long aa = pk2(a, a);
                fma2(acc2[r][0], aa, b.x);
                fma2(acc2[r][1], aa, b.y);
            }
        }
        __syncthreads();
    }

#pragma unroll
    for (int r = 0; r < 8; r++) {
        int n = nbase + r0 + r;
        if (n < NN) {
            float f0, f1, f2, f3;
            upk2(acc2[r][0], f0, f1);
            upk2(acc2[r][1], f2, f3);
            *reinterpret_cast<float4 *>(&out[(size_t)n * 128 + c0]) =
                make_float4(f0, f1, f2, f3);
        }
    }
}

extern "C" void kernel_launch(void *const *d_in, const int *in_sizes, int n_in,
                              void *d_out, int out_size) {
    const float *node_h = (const float *)d_in[0];
    const float *edge_h = (const float *)d_in[1];
    const int   *src    = (const int *)d_in[2];
    const int   *dst    = (const int *)d_in[3];
    const float *We1    = (const float *)d_in[4];
    const float *be1    = (const float *)d_in[5];
    const float *We2    = (const float *)d_in[6];
    const float *be2    = (const float *)d_in[7];
    const float *Wn1    = (const float *)d_in[8];
    const float *bn1    = (const float *)d_in[9];
    const float *Wn2    = (const float *)d_in[10];
    const float *bn2    = (const float *)d_in[11];
    float *out = (float *)d_out;

    zero_agg_kernel<<<1024, 256>>>();
    edge_kernel<<<NE / 64, 256>>>(node_h, edge_h, src, dst, We1, be1, We2, be2);
    node_kernel<<<(NN + 63) / 64, 256>>>(node_h, Wn1, bn1, Wn2, bn2, out);
}

// round 5
// speedup vs baseline: 2.2576x; 2.2559x over previous
#include <cuda_runtime.h>
#include <cstdint>

#define NN 50000
#define NE 640000

__device__ float g_agg[(size_t)NN * 128];
__device__ __align__(16) unsigned short g_nhi[(size_t)NN * 128];
__device__ __align__(16) unsigned short g_nlo[(size_t)NN * 128];
// weight slab images, transposed [128 N x 64 K] bf16 row-major (128B/row):
// We1:0-5, We2:6-7, Wn1:8-11, Wn2:12-13
__device__ __align__(16) unsigned char g_Wh[14 * 16384];
__device__ __align__(16) unsigned char g_Wl[14 * 16384];

static __device__ __forceinline__ uint32_t smem_u32(const void* p) {
    uint32_t a;
    asm("{ .reg .u64 t; cvta.to.shared.u64 t, %1; cvt.u32.u64 %0, t; }" : "=r"(a) : "l"(p));
    return a;
}
static __device__ __forceinline__ uint32_t prmt_hi16(uint32_t a, uint32_t b) {
    uint32_t r; asm("prmt.b32 %0,%1,%2,0x7632;" : "=r"(r) : "r"(a), "r"(b)); return r;
}
static __device__ __forceinline__ float trh(float x) {
    return __uint_as_float(__float_as_uint(x) & 0xFFFF0000u);
}
// result: low16 = bf16(lo_), high16 = bf16(hi_)
static __device__ __forceinline__ uint32_t bf2(float hi_, float lo_) {
    uint32_t r; asm("cvt.rn.bf16x2.f32 %0,%1,%2;" : "=r"(r) : "f"(hi_), "f"(lo_)); return r;
}

#define CPA(dst, src) asm volatile("cp.async.ca.shared.global [%0], [%1], 16;" :: "r"(dst), "l"(src))
#define CPC()         asm volatile("cp.async.commit_group;" ::: "memory")
#define CPW(n)        asm volatile("cp.async.wait_group %0;" :: "n"(n) : "memory")

static __device__ __forceinline__ void ldsm4(uint32_t addr, uint32_t* r) {
    asm volatile("ldmatrix.sync.aligned.m8n8.x4.shared.b16 {%0,%1,%2,%3}, [%4];"
                 : "=r"(r[0]), "=r"(r[1]), "=r"(r[2]), "=r"(r[3]) : "r"(addr));
}
static __device__ __forceinline__ void mma16816(float* d, const uint32_t* a, const uint32_t* b) {
    asm volatile("mma.sync.aligned.m16n8k16.row.col.f32.bf16.bf16.f32 "
                 "{%0,%1,%2,%3},{%4,%5,%6,%7},{%8,%9},{%0,%1,%2,%3};"
                 : "+f"(d[0]), "+f"(d[1]), "+f"(d[2]), "+f"(d[3])
                 : "r"(a[0]), "r"(a[1]), "r"(a[2]), "r"(a[3]), "r"(b[0]), "r"(b[1]));
}

// SMEM layout (dynamic)
#define OFF_DST  0
#define OFF_ROWS 512
#define BUF      18432
#define OFF_AH(b) (2048 + (b) * BUF)            // AH0, AH1 contiguous (Y1H reuse)
#define OFF_AL(b) (2048 + 2 * BUF + (b) * BUF)  // AL0, AL1 contiguous (Y1L reuse)
#define OFF_BH(b) (2048 + 4 * BUF + (b) * BUF)
#define OFF_BL(b) (2048 + 6 * BUF + (b) * BUF)
#define SM_BYTES  (2048 + 8 * BUF)
#define ASTR 144   // A/B slab row stride bytes (64 bf16 + pad)
#define YSTR 272   // y1 row stride bytes (128 bf16 + pad)

// ---- one K=16 chunk, 3-term compensated: 12 LDSM + 48 MMA ----
static __device__ __forceinline__ void mma_chunk(
        uint32_t ahb, uint32_t alb, int astride,
        uint32_t bhb, uint32_t blb,
        int mrow, int nbase, int kb, int bkb, int lane, float acc[2][8][4]) {
    uint32_t ah[2][4], al[2][4], bh[4][4], bl[4][4];
    const int arow = mrow + (lane & 15);
    const int ak   = kb + (lane >> 4) * 16;
#pragma unroll
    for (int mt = 0; mt < 2; mt++) {
        uint32_t off = (uint32_t)((arow + 16 * mt) * astride + ak);
        ldsm4(ahb + off, ah[mt]);
        ldsm4(alb + off, al[mt]);
    }
    const int bn = (lane & 7) + 8 * (lane >> 4);
    const int bk = bkb + ((lane >> 3) & 1) * 16;
#pragma unroll
    for (int nt2 = 0; nt2 < 4; nt2++) {
        uint32_t off = (uint32_t)((nbase + 16 * nt2 + bn) * ASTR + bk);
        ldsm4(bhb + off, bh[nt2]);
        ldsm4(blb + off, bl[nt2]);
    }
#pragma unroll
    for (int mt = 0; mt < 2; mt++)
#pragma unroll
        for (int nt = 0; nt < 8; nt++) {
            const uint32_t* bhp = &bh[nt >> 1][2 * (nt & 1)];
            const uint32_t* blp = &bl[nt >> 1][2 * (nt & 1)];
            mma16816(acc[mt][nt], ah[mt], bhp);
            mma16816(acc[mt][nt], ah[mt], blp);
            mma16816(acc[mt][nt], al[mt], bhp);
        }
}

// ---- slab loaders ----
static __device__ __forceinline__ void load_gather(uint32_t sb, int oh, int ol,
        const int* rows, int koffb, int tid) {   // cp.async 16B gather from g_nhi/g_nlo
    for (int u = tid; u < 2048; u += 256) {
        int isLo = u >> 10, uu = u & 1023, r = uu >> 3, c = uu & 7;
        const unsigned char* g = isLo ? (const unsigned char*)g_nlo : (const unsigned char*)g_nhi;
        CPA(sb + (isLo ? ol : oh) + r * ASTR + c * 16,
            g + (size_t)rows[r] * 256 + koffb + c * 16);
    }
}
static __device__ __forceinline__ void load_W(uint32_t sb, int oh, int ol, int slab, int tid) {
    for (int u = tid; u < 2048; u += 256) {
        int isLo = u >> 10, uu = u & 1023, r = uu >> 3, c = uu & 7;
        const unsigned char* g = (isLo ? g_Wl : g_Wh) + slab * 16384;
        CPA(sb + (isLo ? ol : oh) + r * ASTR + c * 16, g + r * 128 + c * 16);
    }
}
static __device__ __forceinline__ void load_f32split(unsigned char* sm, int oh, int ol,
        const float* base, const int* rows, int rbase, int koff, int tid) {
    for (int u = tid; u < 2048; u += 256) {
        int r = u >> 4, c4 = u & 15;
        size_t row = rows ? (size_t)rows[r] : (size_t)(rbase + r);
        float4 v = *(const float4*)(base + row * 128 + koff + c4 * 4);
        uint2 hi, lo;
        hi.x = prmt_hi16(__float_as_uint(v.x), __float_as_uint(v.y));
        hi.y = prmt_hi16(__float_as_uint(v.z), __float_as_uint(v.w));
        lo.x = bf2(v.y - trh(v.y), v.x - trh(v.x));
        lo.y = bf2(v.w - trh(v.w), v.z - trh(v.z));
        *(uint2*)(sm + oh + r * ASTR + c4 * 8) = hi;
        *(uint2*)(sm + ol + r * ASTR + c4 * 8) = lo;
    }
}

// ---- epilogue1: bias + relu + split -> y1 smem (stride YSTR) ----
static __device__ __forceinline__ void epi_split(float acc[2][8][4], const float* bias,
        unsigned char* sm, int yh, int yl, int mrow, int nbase, int lane) {
    const int ra = mrow + (lane >> 2);
    const int cc = nbase + 2 * (lane & 3);
#pragma unroll
    for (int mt = 0; mt < 2; mt++)
#pragma unroll
        for (int nt = 0; nt < 8; nt++) {
            int c = cc + 8 * nt;
            float b0 = __ldg(&bias[c]), b1 = __ldg(&bias[c + 1]);
#pragma unroll
            for (int h = 0; h < 2; h++) {
                int r = ra + 16 * mt + 8 * h;
                float v0 = fmaxf(acc[mt][nt][2 * h]     + b0, 0.f);
                float v1 = fmaxf(acc[mt][nt][2 * h + 1] + b1, 0.f);
                *(uint32_t*)(sm + yh + r * YSTR + c * 2) =
                    prmt_hi16(__float_as_uint(v0), __float_as_uint(v1));
                *(uint32_t*)(sm + yl + r * YSTR + c * 2) =
                    bf2(v1 - trh(v1), v0 - trh(v0));
            }
        }
}

// ---- prep kernels ----
__global__ void zero_agg_kernel() {
    size_t stride = (size_t)gridDim.x * blockDim.x * 4;
    for (size_t i = (size_t)(blockIdx.x * blockDim.x + threadIdx.x) * 4;
         i < (size_t)NN * 128; i += stride)
        *(float4*)&g_agg[i] = make_float4(0.f, 0.f, 0.f, 0.f);
}
__global__ void prep_weights_kernel(const float* __restrict__ We1, const float* __restrict__ We2,
                                    const float* __restrict__ Wn1, const float* __restrict__ Wn2) {
    int s = blockIdx.x;
    const float* W; int slab;
    if (s < 6)       { W = We1; slab = s; }
    else if (s < 8)  { W = We2; slab = s - 6; }
    else if (s < 12) { W = Wn1; slab = s - 8; }
    else             { W = Wn2; slab = s - 12; }
    unsigned char* ph = g_Wh + s * 16384;
    unsigned char* pl = g_Wl + s * 16384;
    int k0 = slab * 64;
    for (int p = threadIdx.x; p < 4096; p += blockDim.x) {
        int n = p >> 5, kk = (p & 31) << 1;
        float x0 = W[(size_t)(k0 + kk) * 128 + n];
        float x1 = W[(size_t)(k0 + kk + 1) * 128 + n];
        *(uint32_t*)(ph + n * 128 + kk * 2) = prmt_hi16(__float_as_uint(x0), __float_as_uint(x1));
        *(uint32_t*)(pl + n * 128 + kk * 2) = bf2(x1 - trh(x1), x0 - trh(x0));
    }
}
__global__ void prep_node_kernel(const float* __restrict__ node_h) {
    size_t i = (size_t)blockIdx.x * blockDim.x + threadIdx.x;
    if (i >= (size_t)NN * 32) return;
    float4 v = ((const float4*)node_h)[i];
    uint2 hi, lo;
    hi.x = prmt_hi16(__float_as_uint(v.x), __float_as_uint(v.y));
    hi.y = prmt_hi16(__float_as_uint(v.z), __float_as_uint(v.w));
    lo.x = bf2(v.y - trh(v.y), v.x - trh(v.x));
    lo.y = bf2(v.w - trh(v.w), v.z - trh(v.z));
    ((uint2*)g_nhi)[i] = hi;
    ((uint2*)g_nlo)[i] = lo;
}

// ---- edge kernel: 128 edges x 128 cols per block ----
__global__ __launch_bounds__(256, 1)
void edge_kernel(const float* __restrict__ edge_h,
                 const int* __restrict__ src, const int* __restrict__ dst,
                 const float* __restrict__ be1, const float* __restrict__ be2) {
    extern __shared__ __align__(1024) unsigned char sm[];
    const uint32_t sb = smem_u32(sm);
    const int tid = threadIdx.x, wid = tid >> 5, lane = tid & 31;
    const int ebase = blockIdx.x << 7;
    const int mrow = (wid >> 1) << 5;     // 0,32,64,96
    const int nbase = (wid & 1) << 6;     // 0,64

    int* dstS  = (int*)(sm + OFF_DST);
    int* rowsS = (int*)(sm + OFF_ROWS);
    if (tid < 128) {
        rowsS[tid] = src[ebase + tid];
        dstS[tid]  = dst[ebase + tid];
    }
    __syncthreads();

    float acc[2][8][4];
#pragma unroll
    for (int mt = 0; mt < 2; mt++)
#pragma unroll
        for (int nt = 0; nt < 8; nt++)
#pragma unroll
            for (int q = 0; q < 4; q++) acc[mt][nt][q] = 0.f;

    // slab s: 0,1 = src k0/k64 ; 2,3 = dst k0/k64 ; 4,5 = edge_h k0/k64
    auto load_slab = [&](int s, int b) {
        if (s < 2)      load_gather(sb, OFF_AH(b), OFF_AL(b), rowsS, (s & 1) << 7, tid);
        else if (s < 4) load_gather(sb, OFF_AH(b), OFF_AL(b), dstS,  (s & 1) << 7, tid);
        else            load_f32split(sm, OFF_AH(b), OFF_AL(b), edge_h, nullptr, ebase,
                                      (s - 4) << 6, tid);
        load_W(sb, OFF_BH(b), OFF_BL(b), s, tid);
    };

    load_slab(0, 0); CPC();
    for (int s = 0; s < 6; s++) {
        const int b = s & 1;
        if (s < 5) { load_slab(s + 1, b ^ 1); CPC(); CPW(1); } else CPW(0);
        __syncthreads();
        for (int c = 0; c < 4; c++)
            mma_chunk(sb + OFF_AH(b), sb + OFF_AL(b), ASTR,
                      sb + OFF_BH(b), sb + OFF_BL(b),
                      mrow, nbase, c * 32, c * 32, lane, acc);
        __syncthreads();
    }

    // kick off We2 loads into both B buffers, then write y1
    load_W(sb, OFF_BH(0), OFF_BL(0), 6, tid);
    load_W(sb, OFF_BH(1), OFF_BL(1), 7, tid);
    CPC();
    epi_split(acc, be1, sm, OFF_AH(0), OFF_AL(0), mrow, nbase, lane);
    CPW(0);
    __syncthreads();

    float acc2[2][8][4];
#pragma unroll
    for (int mt = 0; mt < 2; mt++)
#pragma unroll
        for (int nt = 0; nt < 8; nt++)
#pragma unroll
            for (int q = 0; q < 4; q++) acc2[mt][nt][q] = 0.f;

    for (int c = 0; c < 8; c++)
        mma_chunk(sb + OFF_AH(0), sb + OFF_AL(0), YSTR,
                  sb + OFF_BH(c >> 2), sb + OFF_BL(c >> 2),
                  mrow, nbase, c * 32, (c & 3) * 32, lane, acc2);

    // epilogue2: + be2, scatter-add to g_agg[dst]
    const int ra = mrow + (lane >> 2);
    const int cc = nbase + 2 * (lane & 3);
#pragma unroll
    for (int mt = 0; mt < 2; mt++)
#pragma unroll
        for (int nt = 0; nt < 8; nt++) {
            int c = cc + 8 * nt;
            float b0 = __ldg(&be2[c]), b1 = __ldg(&be2[c + 1]);
#pragma unroll
            for (int h = 0; h < 2; h++) {
                int r = ra + 16 * mt + 8 * h;
                float* gp = g_agg + (size_t)dstS[r] * 128 + c;
                atomicAdd(gp,     acc2[mt][nt][2 * h]     + b0);
                atomicAdd(gp + 1, acc2[mt][nt][2 * h + 1] + b1);
            }
        }
}

// ---- node kernel: 128 nodes x 128 cols, K=256 = [agg | node_h] ----
__global__ __launch_bounds__(256, 1)
void node_kernel(const float* __restrict__ bn1, const float* __restrict__ bn2,
                 float* __restrict__ out) {
    extern __shared__ __align__(1024) unsigned char sm[];
    const uint32_t sb = smem_u32(sm);
    const int tid = threadIdx.x, wid = tid >> 5, lane = tid & 31;
    const int nbase0 = blockIdx.x << 7;
    const int mrow = (wid >> 1) << 5;
    const int nbase = (wid & 1) << 6;

    int* rowsS = (int*)(sm + OFF_ROWS);
    if (tid < 128) {
        int n = nbase0 + tid; if (n >= NN) n = NN - 1;
        rowsS[tid] = n;
    }
    __syncthreads();

    float acc[2][8][4];
#pragma unroll
    for (int mt = 0; mt < 2; mt++)
#pragma unroll
        for (int nt = 0; nt < 8; nt++)
#pragma unroll
            for (int q = 0; q < 4; q++) acc[mt][nt][q] = 0.f;

    // slabs: 0,1 = agg k0/k64 (split on fly), 2,3 = node rows (cp gather)
    auto load_slab = [&](int s, int b) {
        if (s < 2) load_f32split(sm, OFF_AH(b), OFF_AL(b), g_agg, rowsS, 0, s << 6, tid);
        else       load_gather(sb, OFF_AH(b), OFF_AL(b), rowsS, (s & 1) << 7, tid);
        load_W(sb, OFF_BH(b), OFF_BL(b), 8 + s, tid);
    };

    load_slab(0, 0); CPC();
    for (int s = 0; s < 4; s++) {
        const int b = s & 1;
        if (s < 3) { load_slab(s + 1, b ^ 1); CPC(); CPW(1); } else CPW(0);
        __syncthreads();
        for (int c = 0; c < 4; c++)
            mma_chunk(sb + OFF_AH(b), sb + OFF_AL(b), ASTR,
                      sb + OFF_BH(b), sb + OFF_BL(b),
                      mrow, nbase, c * 32, c * 32, lane, acc);
        __syncthreads();
    }

    load_W(sb, OFF_BH(0), OFF_BL(0), 12, tid);
    load_W(sb, OFF_BH(1), OFF_BL(1), 13, tid);
    CPC();
    epi_split(acc, bn1, sm, OFF_AH(0), OFF_AL(0), mrow, nbase, lane);
    CPW(0);
    __syncthreads();

    float acc2[2][8][4];
#pragma unroll
    for (int mt = 0; mt < 2; mt++)
#pragma unroll
        for (int nt = 0; nt < 8; nt++)
#pragma unroll
            for (int q = 0; q < 4; q++) acc2[mt][nt][q] = 0.f;

    for (int c = 0; c < 8; c++)
        mma_chunk(sb + OFF_AH(0), sb + OFF_AL(0), YSTR,
                  sb + OFF_BH(c >> 2), sb + OFF_BL(c >> 2),
                  mrow, nbase, c * 32, (c & 3) * 32, lane, acc2);

    const int ra = mrow + (lane >> 2);
    const int cc = nbase + 2 * (lane & 3);
#pragma unroll
    for (int mt = 0; mt < 2; mt++)
#pragma unroll
        for (int nt = 0; nt < 8; nt++) {
            int c = cc + 8 * nt;
            float b0 = __ldg(&bn2[c]), b1 = __ldg(&bn2[c + 1]);
#pragma unroll
            for (int h = 0; h < 2; h++) {
                int r = ra + 16 * mt + 8 * h;
                int n = nbase0 + r;
                if (n < NN) {
                    float2 v = make_float2(acc2[mt][nt][2 * h]     + b0,
                                           acc2[mt][nt][2 * h + 1] + b1);
                    *(float2*)(out + (size_t)n * 128 + c) = v;
                }
            }
        }
}

extern "C" void kernel_launch(void* const* d_in, const int* in_sizes, int n_in,
                              void* d_out, int out_size) {
    const float* node_h = (const float*)d_in[0];
    const float* edge_h = (const float*)d_in[1];
    const int*   src    = (const int*)d_in[2];
    const int*   dst    = (const int*)d_in[3];
    const float* We1    = (const float*)d_in[4];
    const float* be1    = (const float*)d_in[5];
    const float* We2    = (const float*)d_in[6];
    const float* be2    = (const float*)d_in[7];
    const float* Wn1    = (const float*)d_in[8];
    const float* bn1    = (const float*)d_in[9];
    const float* Wn2    = (const float*)d_in[10];
    const float* bn2    = (const float*)d_in[11];
    float* out = (float*)d_out;

    cudaFuncSetAttribute(edge_kernel, cudaFuncAttributeMaxDynamicSharedMemorySize, SM_BYTES);
    cudaFuncSetAttribute(node_kernel, cudaFuncAttributeMaxDynamicSharedMemorySize, SM_BYTES);

    zero_agg_kernel<<<1024, 256>>>();
    prep_weights_kernel<<<14, 256>>>(We1, We2, Wn1, Wn2);
    prep_node_kernel<<<6250, 256>>>(node_h);
    edge_kernel<<<NE / 128, 256, SM_BYTES>>>(edge_h, src, dst, be1, be2);
    node_kernel<<<(NN + 127) / 128, 256, SM_BYTES>>>(bn1, bn2, out);
}